// round 12
// baseline (speedup 1.0000x reference)
#include <cuda_runtime.h>
#include <cuda_bf16.h>

#define LL   128
#define BSZ  2
#define EE   768
#define HH   12
#define EH   384              // E/2
#define BHH  24               // B*H

// ---------------- scratch (device globals; no allocation allowed) -----------
__device__ float g_nq[256 * EE];            // conv1d(query) output, (L,B,E)
__device__ float g_proj[256 * 4 * EH];      // [q | k | v | e] per row, (256,1536)
__device__ float g_dq[BHH * LL];
__device__ float g_dk[BHH * LL];
__device__ float g_de[LL * BHH];
__device__ float g_a[256 * EE];             // attention output in (L,B,E)
__device__ float g_y[256 * EE];             // deconv output

// ---------------- packed f32x2 helpers (attn kernel) -------------------------
#define FMA2(d, a, b) asm("fma.rn.f32x2 %0, %1, %2, %3;" \
                          : "=l"(d) : "l"(a), "l"(b), "l"(d))
#define PACK2(d, lo, hi) asm("mov.b64 %0, {%1, %2};" : "=l"(d) : "f"(lo), "f"(hi))
#define UNPK(lo, hi, s) asm("mov.b64 {%0, %1}, %2;" : "=f"(lo), "=f"(hi) : "l"(s))

// ---------------- bf16 mma.sync m16n8k16 ------------------------------------
__device__ __forceinline__ void mma16(float* d, const unsigned* a, const unsigned* b)
{
    asm volatile("mma.sync.aligned.m16n8k16.row.col.f32.bf16.bf16.f32 "
                 "{%0,%1,%2,%3}, {%4,%5,%6,%7}, {%8,%9}, {%0,%1,%2,%3};"
                 : "+f"(d[0]), "+f"(d[1]), "+f"(d[2]), "+f"(d[3])
                 : "r"(a[0]), "r"(a[1]), "r"(a[2]), "r"(a[3]),
                   "r"(b[0]), "r"(b[1]));
}

// split fp32 pair -> packed bf16 hi word + packed bf16 lo word (lo = a - hi)
__device__ __forceinline__ void bsplit(float2 v, unsigned& h, unsigned& l)
{
    __nv_bfloat16 h0 = __float2bfloat16(v.x);
    __nv_bfloat16 h1 = __float2bfloat16(v.y);
    float r0 = v.x - __bfloat162float(h0);
    float r1 = v.y - __bfloat162float(h1);
    __nv_bfloat162 hh; hh.x = h0; hh.y = h1;
    __nv_bfloat162 ll; ll.x = __float2bfloat16(r0); ll.y = __float2bfloat16(r1);
    h = *(unsigned*)&hh;
    l = *(unsigned*)&ll;
}

// ---------------- init: zero atomic-accumulation targets ---------------------
__global__ __launch_bounds__(256)
void init_a_kernel()
{
    const int idx = blockIdx.x * 256 + threadIdx.x;   // 98304 float4
    float4 z = {0.f, 0.f, 0.f, 0.f};
    if (idx < 49152) ((float4*)g_nq)[idx] = z;
    else             ((float4*)g_y)[idx - 49152] = z;
}
__global__ __launch_bounds__(256)
void init_b_kernel(float* __restrict__ out)
{
    const int idx = blockIdx.x * 256 + threadIdx.x;   // 147456 float4
    float4 z = {0.f, 0.f, 0.f, 0.f};
    if (idx < 49152) ((float4*)out)[idx] = z;
    else             ((float4*)g_proj)[idx - 49152] = z;
}

// ---------------- tensor-core GEMM, tile 32x64, BK=32, 4 warps ---------------
// bf16 3-term split computed ONCE in the loader; packed 2-per-word (k-pairs).
// smem words [row][word], stride 20: frag reads bank (grp*20+thr4)%32 distinct.
// Inner loop per k16: 24 LDS.32 + 12 HMMA.16816, zero ALU.
// MODE 0: nq   = conv(query)      M=256 N=768  K=1536  KSPLIT=8
// MODE 1: proj = [q|k|v|e]        M=256 N=1536 K=768   KSPLIT=4
// MODE 2: y    = deconv(a)        M=256 N=768  K=1536  KSPLIT=8
// MODE 3: out  = y @ out_w^T      M=256 N=768  K=768   KSPLIT=4
template<int MODE, int KSPLIT>
__global__ __launch_bounds__(128, 5)
void gemm_kernel(const float* __restrict__ A0,
                 const float* __restrict__ W0,
                 const float* __restrict__ W1,
                 const float* __restrict__ W2,
                 const float* __restrict__ W3,
                 const float* __restrict__ bb0,
                 const float* __restrict__ bb1,
                 const float* __restrict__ bb2,
                 const float* __restrict__ bb3,
                 float* __restrict__ Cout)
{
    constexpr int BM = 32, BN = 64, BK = 32;
    constexpr int N  = (MODE == 1) ? 1536 : 768;
    constexpr int K  = (MODE == 0 || MODE == 2) ? 1536 : 768;
    constexpr int NT = K / KSPLIT / BK;
    constexpr int STR = 20;    // words per row (16 data + 4 pad): conflict-free

    __shared__ __align__(16) unsigned AhS[2][BM * STR], AlS[2][BM * STR];
    __shared__ __align__(16) unsigned BhS[2][BN * STR], BlS[2][BN * STR];

    const int bn   = blockIdx.x * BN;
    const int bm   = blockIdx.y * BM;
    const int koff = blockIdx.z * (K / KSPLIT);
    const int tid  = threadIdx.x;
    const int lane = tid & 31;
    const int wid  = tid >> 5;            // 0..3
    const int rb   = (wid & 1) * 16;      // warp row base
    const int cbB  = (wid >> 1) * 32;     // warp col base
    const int grp  = lane >> 2;           // 0..7
    const int thr4 = lane & 3;            // 0..3

    // loader coordinates: word index + row/col fragment
    const int wIdx = tid & 15;            // word within row (covers k pair)
    const int fSub = tid >> 4;            // 0..7

    float2 arf[4], brf[8];

    auto loadA = [&](int t) {
        const int k = koff + t * BK + 2 * wIdx;
        #pragma unroll
        for (int i = 0; i < 4; i++) {
            const int row = bm + i * 8 + fSub;
            float2 v;
            if (MODE == 0) {
                if (k < EE) v = (row >= BSZ) ? *(const float2*)&A0[(row - BSZ) * EE + k]
                                             : make_float2(0.f, 0.f);
                else        v = *(const float2*)&A0[row * EE + (k - EE)];
            } else if (MODE == 1) {
                const float* Ap = (bn >= 3 * EH) ? A0 : g_nq;
                v = *(const float2*)&Ap[row * EE + k];
            } else if (MODE == 2) {
                if (k < EE) v = *(const float2*)&g_a[row * EE + k];
                else        v = (row >= BSZ) ? *(const float2*)&g_a[(row - BSZ) * EE + (k - EE)]
                                             : make_float2(0.f, 0.f);
            } else {
                v = *(const float2*)&g_y[row * EE + k];
            }
            arf[i] = v;
        }
    };

    auto loadB = [&](int t) {
        const int k = koff + t * BK + 2 * wIdx;
        #pragma unroll
        for (int i = 0; i < 8; i++) {
            const int o = bn + i * 8 + fSub;
            float2 v;
            if (MODE == 0) {
                // conv_w (o, k_in, 2): stride-2 scalar pair
                const float* base = (k < EE) ? W0 + (o * EE + k) * 2
                                             : W0 + (o * EE + (k - EE)) * 2 + 1;
                v.x = base[0]; v.y = base[2];
            } else if (MODE == 1) {
                const float* Wp; int oo = o;
                if (o < EH)          Wp = W0;
                else if (o < 2 * EH) { Wp = W1; oo = o - EH; }
                else if (o < 3 * EH) { Wp = W2; oo = o - 2 * EH; }
                else                 { Wp = W3; oo = o - 3 * EH; }
                v = *(const float2*)&Wp[oo * EE + k];
            } else if (MODE == 2) {
                // deconv_w (k_in, o, 2): k-adjacent stride = 2*EE
                const float* base = (k < EE) ? W0 + (k * EE + o) * 2
                                             : W0 + ((k - EE) * EE + o) * 2 + 1;
                v.x = base[0]; v.y = base[2 * EE];
            } else {
                v = *(const float2*)&W0[o * EE + k];
            }
            brf[i] = v;
        }
    };

    auto storeTiles = [&](int nb) {
        #pragma unroll
        for (int i = 0; i < 4; i++) {
            unsigned h, l; bsplit(arf[i], h, l);
            const int off = (i * 8 + fSub) * STR + wIdx;
            AhS[nb][off] = h; AlS[nb][off] = l;
        }
        #pragma unroll
        for (int i = 0; i < 8; i++) {
            unsigned h, l; bsplit(brf[i], h, l);
            const int off = (i * 8 + fSub) * STR + wIdx;
            BhS[nb][off] = h; BlS[nb][off] = l;
        }
    };

    float dm[4][4] = {};   // hi*hi accumulators (per n-tile)
    float dc[4][4] = {};   // hi*lo + lo*hi corrections

    loadA(0); loadB(0);
    storeTiles(0);
    __syncthreads();

    int buf = 0;
    for (int t = 0; t < NT; t++) {
        if (t + 1 < NT) { loadA(t + 1); loadB(t + 1); }

        #pragma unroll
        for (int k16 = 0; k16 < 2; k16++) {
            const int wb = k16 * 8 + thr4;
            const int r0i = (rb + grp) * STR + wb;
            const int r1i = (rb + grp + 8) * STR + wb;
            unsigned ah[4], al[4];
            ah[0] = AhS[buf][r0i];     ah[1] = AhS[buf][r1i];
            ah[2] = AhS[buf][r0i + 4]; ah[3] = AhS[buf][r1i + 4];
            al[0] = AlS[buf][r0i];     al[1] = AlS[buf][r1i];
            al[2] = AlS[buf][r0i + 4]; al[3] = AlS[buf][r1i + 4];
            #pragma unroll
            for (int nt = 0; nt < 4; nt++) {
                const int ci = (cbB + nt * 8 + grp) * STR + wb;
                unsigned bh[2] = {BhS[buf][ci], BhS[buf][ci + 4]};
                unsigned bl[2] = {BlS[buf][ci], BlS[buf][ci + 4]};
                mma16(dm[nt], ah, bh);
                mma16(dc[nt], ah, bl);
                mma16(dc[nt], al, bh);
            }
        }

        if (t + 1 < NT) {
            storeTiles(buf ^ 1);
            __syncthreads();
            buf ^= 1;
        }
    }

    // ---- epilogue: atomic accumulate (+bias on z==0) ----------------------------
    float* C = (MODE == 0) ? g_nq : (MODE == 1) ? g_proj
             : (MODE == 2) ? g_y  : Cout;

    #pragma unroll
    for (int nt = 0; nt < 4; nt++) {
        const int col = bn + cbB + nt * 8 + 2 * thr4;
        float bias0, bias1;
        if (MODE == 1) {
            const int seg = col / EH;                  // EH not pow2: no masking
            const float* bp = (seg == 0) ? bb0 : (seg == 1) ? bb1
                            : (seg == 2) ? bb2 : bb3;
            const int ob = col - seg * EH;
            bias0 = bp[ob]; bias1 = bp[ob + 1];
        } else {
            bias0 = bb0[col]; bias1 = bb0[col + 1];
        }
        if (blockIdx.z != 0) { bias0 = 0.f; bias1 = 0.f; }

        const int row = bm + rb + grp;
        atomicAdd(&C[row * N + col],           dm[nt][0] + dc[nt][0] + bias0);
        atomicAdd(&C[row * N + col + 1],       dm[nt][1] + dc[nt][1] + bias1);
        atomicAdd(&C[(row + 8) * N + col],     dm[nt][2] + dc[nt][2] + bias0);
        atomicAdd(&C[(row + 8) * N + col + 1], dm[nt][3] + dc[nt][3] + bias1);
    }
}

// ---------------- dq / dk / de precompute (9216 length-64 dots) -------------
__global__ __launch_bounds__(256)
void dots_kernel(const float* __restrict__ entity,
                 const float* __restrict__ attn_w)
{
    int w    = (blockIdx.x * blockDim.x + threadIdx.x) >> 5;
    int lane = threadIdx.x & 31;
    if (w >= 3 * BHH * LL) return;
    int which = w / (BHH * LL);
    int idx   = w % (BHH * LL);
    float v;
    if (which < 2) {
        int m = idx >> 7, x = idx & 127;
        int b = m / HH, h = m % HH;
        int row = x * BSZ + b;
        int base = (h < 6) ? (row * 1536 + which * EH + h * 64)
                           : (row * 1536 + 3 * EH + (h - 6) * 64);
        const float* wv = attn_w + which * 64;
        v = g_proj[base + lane] * wv[lane] + g_proj[base + lane + 32] * wv[lane + 32];
    } else {
        int i = idx / BHH, s = idx % BHH;
        int b = s / HH, h = s % HH;
        int base = (i * BSZ + b) * EE + h * 64;
        v = entity[base + lane] * attn_w[128 + lane]
          + entity[base + lane + 32] * attn_w[128 + lane + 32];
    }
    #pragma unroll
    for (int off = 16; off; off >>= 1) v += __shfl_down_sync(0xffffffffu, v, off);
    if (lane == 0) {
        if (which == 0)      g_dq[idx] = v;
        else if (which == 1) g_dk[idx] = v;
        else                 g_de[idx] = v;
    }
}

// ---------------- fused attention: 16 rows per block ------------------------
__global__ __launch_bounds__(256)
void attn_kernel(const float* __restrict__ attn_b)
{
    __shared__ float sT[3072];       // dk - de
    __shared__ float sqe[64];        // dq + de for the block's 2 i_src values
    __shared__ __align__(8) float sp[16][128];   // normalized probs

    const int ig  = blockIdx.x;      // 0..7 (16-row group)
    const int bh  = blockIdx.y;      // 0..23
    const int tid = threadIdx.x;
    const int g0  = bh * 16384 + ig * 2048;
    const int i_src0 = g0 / 3072;

    for (int x = tid; x < 3072; x += 256) sT[x] = g_dk[x] - g_de[x];
    if (tid < 48) {
        const int il = tid / 24, s = tid - il * 24;
        const int isrc = min(i_src0 + il, LL - 1);
        sqe[tid] = g_dq[s * 128 + isrc] + g_de[isrc * 24 + s];
    }
    __syncthreads();
    const float bias = attn_b[0];

    const int lane = tid & 31, w = tid >> 5;
    #pragma unroll
    for (int rr = 0; rr < 2; rr++) {
        const int r  = w + rr * 8;
        const int gb = g0 + r * 128;
        float sc[4];
        #pragma unroll
        for (int q = 0; q < 4; q++) {
            const int g    = gb + q * 32 + lane;
            const int isrc = g / 3072;
            const int rem  = g - isrc * 3072;
            const int s    = rem % 24;
            float v = sqe[(isrc - i_src0) * 24 + s] + sT[rem] + bias;
            sc[q] = (v >= 0.f) ? v : 0.01f * v;
        }
        float m = fmaxf(fmaxf(sc[0], sc[1]), fmaxf(sc[2], sc[3]));
        #pragma unroll
        for (int off = 16; off; off >>= 1)
            m = fmaxf(m, __shfl_xor_sync(0xffffffffu, m, off));
        float e[4], sum = 0.f;
        #pragma unroll
        for (int q = 0; q < 4; q++) { e[q] = __expf(sc[q] - m); sum += e[q]; }
        #pragma unroll
        for (int off = 16; off; off >>= 1)
            sum += __shfl_xor_sync(0xffffffffu, sum, off);
        const float inv = 1.f / sum;
        #pragma unroll
        for (int q = 0; q < 4; q++) sp[r][q * 32 + lane] = e[q] * inv;
    }
    __syncthreads();

    const int b = bh / HH, h = bh - (bh / HH) * HH;
    const int off = (h < 6) ? (2 * EH + h * 64) : (3 * EH + (h - 6) * 64);
    const int d  = tid & 63;
    const int r0 = (tid >> 6) * 4;   // 0,4,8,12
    const float* Vp = g_proj + b * 1536 + off + d;

    unsigned long long acc2[4] = {};
    #pragma unroll 4
    for (int jj = 0; jj < 128; jj += 2) {
        const float v0 = Vp[jj * 3072];
        const float v1 = Vp[(jj + 1) * 3072];
        unsigned long long vv;
        PACK2(vv, v0, v1);
        #pragma unroll
        for (int r = 0; r < 4; r++) {
            const unsigned long long pp = *(const unsigned long long*)&sp[r0 + r][jj];
            FMA2(acc2[r], pp, vv);
        }
    }
    #pragma unroll
    for (int r = 0; r < 4; r++) {
        float lo, hi;
        UNPK(lo, hi, acc2[r]);
        const int i2 = ig * 16 + r0 + r;
        g_a[(i2 * BSZ + b) * EE + h * 64 + d] = lo + hi;
    }
}

// ---------------- launcher ---------------------------------------------------
extern "C" void kernel_launch(void* const* d_in, const int* in_sizes, int n_in,
                              void* d_out, int out_size)
{
    const float* query    = (const float*)d_in[0];
    const float* entity   = (const float*)d_in[1];
    const float* conv_w   = (const float*)d_in[2];
    const float* conv_b   = (const float*)d_in[3];
    const float* q_w      = (const float*)d_in[4];
    const float* q_b      = (const float*)d_in[5];
    const float* k_w      = (const float*)d_in[6];
    const float* k_b      = (const float*)d_in[7];
    const float* v_w      = (const float*)d_in[8];
    const float* v_b      = (const float*)d_in[9];
    const float* e_w      = (const float*)d_in[10];
    const float* e_b      = (const float*)d_in[11];
    const float* attn_w   = (const float*)d_in[12];
    const float* attn_b   = (const float*)d_in[13];
    const float* deconv_w = (const float*)d_in[14];
    const float* deconv_b = (const float*)d_in[15];
    const float* out_w    = (const float*)d_in[16];
    const float* out_b    = (const float*)d_in[17];
    float* out = (float*)d_out;

    init_a_kernel<<<384, 256>>>();                 // slot 0
    init_b_kernel<<<576, 256>>>(out);              // slot 1
    gemm_kernel<0, 8><<<dim3(12, 8, 8), 128>>>(query, conv_w, nullptr, nullptr, nullptr,
                                               conv_b, nullptr, nullptr, nullptr, nullptr);  // slot 2
    gemm_kernel<1, 4><<<dim3(24, 8, 4), 128>>>(entity, q_w, k_w, v_w, e_w,
                                               q_b, k_b, v_b, e_b, nullptr);                 // slot 3 (profiled)
    dots_kernel<<<1152, 256>>>(entity, attn_w);
    attn_kernel<<<dim3(8, BHH), 256>>>(attn_b);
    gemm_kernel<2, 8><<<dim3(12, 8, 8), 128>>>(nullptr, deconv_w, nullptr, nullptr, nullptr,
                                               deconv_b, nullptr, nullptr, nullptr, nullptr);
    gemm_kernel<3, 4><<<dim3(12, 8, 4), 128>>>(nullptr, out_w, nullptr, nullptr, nullptr,
                                               out_b, nullptr, nullptr, nullptr, out);
}

// round 13
// speedup vs baseline: 1.1842x; 1.1842x over previous
#include <cuda_runtime.h>
#include <cuda_bf16.h>

#define LL   128
#define BSZ  2
#define EE   768
#define HH   12
#define EH   384              // E/2
#define BHH  24               // B*H

// ---------------- scratch (device globals; no allocation allowed) -----------
__device__ float g_nq[256 * EE];            // conv1d(query) output, (L,B,E)
__device__ float g_proj[256 * 4 * EH];      // [q | k | v | e] per row, (256,1536)
__device__ float g_dq[BHH * LL];
__device__ float g_dk[BHH * LL];
__device__ float g_de[LL * BHH];
__device__ float g_a[256 * EE];             // attention output in (L,B,E)
__device__ float g_y[256 * EE];             // deconv output

// ---------------- packed f32x2 helpers (attn kernel) -------------------------
#define FMA2(d, a, b) asm("fma.rn.f32x2 %0, %1, %2, %3;" \
                          : "=l"(d) : "l"(a), "l"(b), "l"(d))
#define PACK2(d, lo, hi) asm("mov.b64 %0, {%1, %2};" : "=l"(d) : "f"(lo), "f"(hi))
#define UNPK(lo, hi, s) asm("mov.b64 {%0, %1}, %2;" : "=f"(lo), "=f"(hi) : "l"(s))

// ---------------- bf16 mma.sync m16n8k16 ------------------------------------
__device__ __forceinline__ void mma16(float* d, const unsigned* a, const unsigned* b)
{
    asm volatile("mma.sync.aligned.m16n8k16.row.col.f32.bf16.bf16.f32 "
                 "{%0,%1,%2,%3}, {%4,%5,%6,%7}, {%8,%9}, {%0,%1,%2,%3};"
                 : "+f"(d[0]), "+f"(d[1]), "+f"(d[2]), "+f"(d[3])
                 : "r"(a[0]), "r"(a[1]), "r"(a[2]), "r"(a[3]),
                   "r"(b[0]), "r"(b[1]));
}

// split fp32 pair -> packed bf16 hi word + packed bf16 lo word (lo = a - hi)
__device__ __forceinline__ void bsplit(float2 v, unsigned& h, unsigned& l)
{
    __nv_bfloat16 h0 = __float2bfloat16(v.x);
    __nv_bfloat16 h1 = __float2bfloat16(v.y);
    float r0 = v.x - __bfloat162float(h0);
    float r1 = v.y - __bfloat162float(h1);
    __nv_bfloat162 hh; hh.x = h0; hh.y = h1;
    __nv_bfloat162 ll; ll.x = __float2bfloat16(r0); ll.y = __float2bfloat16(r1);
    h = *(unsigned*)&hh;
    l = *(unsigned*)&ll;
}

// ---------------- init: zero atomic-accumulation targets ---------------------
__global__ __launch_bounds__(256)
void init_a_kernel()
{
    const int idx = blockIdx.x * 256 + threadIdx.x;   // 98304 float4
    float4 z = {0.f, 0.f, 0.f, 0.f};
    if (idx < 49152) ((float4*)g_nq)[idx] = z;
    else             ((float4*)g_y)[idx - 49152] = z;
}
__global__ __launch_bounds__(256)
void init_b_kernel(float* __restrict__ out)
{
    const int idx = blockIdx.x * 256 + threadIdx.x;   // 147456 float4
    float4 z = {0.f, 0.f, 0.f, 0.f};
    if (idx < 49152) ((float4*)out)[idx] = z;
    else             ((float4*)g_proj)[idx - 49152] = z;
}

// ---------------- tensor-core GEMM, tile 32x64, BK=32, 4 warps ---------------
// bf16 3-term split computed ONCE in the loader; packed 2-per-word (k-pairs).
// smem words [row][word], stride 20. Inner loop per k16: 24 LDS + 12 HMMA.
// R13: coalesced B loaders for conv (float4 dual-tap) and deconv (o-major).
// MODE 0: nq   = conv(query)      M=256 N=768  K=1536  KSPLIT=8
// MODE 1: proj = [q|k|v|e]        M=256 N=1536 K=768   KSPLIT=4
// MODE 2: y    = deconv(a)        M=256 N=768  K=1536  KSPLIT=8
// MODE 3: out  = y @ out_w^T      M=256 N=768  K=768   KSPLIT=4
template<int MODE, int KSPLIT>
__global__ __launch_bounds__(128, 5)
void gemm_kernel(const float* __restrict__ A0,
                 const float* __restrict__ W0,
                 const float* __restrict__ W1,
                 const float* __restrict__ W2,
                 const float* __restrict__ W3,
                 const float* __restrict__ bb0,
                 const float* __restrict__ bb1,
                 const float* __restrict__ bb2,
                 const float* __restrict__ bb3,
                 float* __restrict__ Cout)
{
    constexpr int BM = 32, BN = 64, BK = 32;
    constexpr int N  = (MODE == 1) ? 1536 : 768;
    constexpr int K  = (MODE == 0 || MODE == 2) ? 1536 : 768;
    constexpr int NT = K / KSPLIT / BK;
    constexpr int STR = 20;    // words per row (16 data + 4 pad)

    __shared__ __align__(16) unsigned AhS[2][BM * STR], AlS[2][BM * STR];
    __shared__ __align__(16) unsigned BhS[2][BN * STR], BlS[2][BN * STR];

    const int bn   = blockIdx.x * BN;
    const int bm   = blockIdx.y * BM;
    const int koff = blockIdx.z * (K / KSPLIT);
    const int tid  = threadIdx.x;
    const int lane = tid & 31;
    const int wid  = tid >> 5;            // 0..3
    const int rb   = (wid & 1) * 16;      // warp row base
    const int cbB  = (wid >> 1) * 32;     // warp col base
    const int grp  = lane >> 2;           // 0..7
    const int thr4 = lane & 3;            // 0..3

    // loader coordinates
    const int wIdx = tid & 15;            // word within row (covers k pair)
    const int fSub = tid >> 4;            // 0..7
    const int oIdx = tid & 63;            // MODE 2: owned o
    const int oWh  = tid >> 6;            // MODE 2: word half 0..1

    float2 arf[4], brf[8];

    auto loadA = [&](int t) {
        const int k = koff + t * BK + 2 * wIdx;
        #pragma unroll
        for (int i = 0; i < 4; i++) {
            const int row = bm + i * 8 + fSub;
            float2 v;
            if (MODE == 0) {
                if (k < EE) v = (row >= BSZ) ? *(const float2*)&A0[(row - BSZ) * EE + k]
                                             : make_float2(0.f, 0.f);
                else        v = *(const float2*)&A0[row * EE + (k - EE)];
            } else if (MODE == 1) {
                const float* Ap = (bn >= 3 * EH) ? A0 : g_nq;
                v = *(const float2*)&Ap[row * EE + k];
            } else if (MODE == 2) {
                if (k < EE) v = *(const float2*)&g_a[row * EE + k];
                else        v = (row >= BSZ) ? *(const float2*)&g_a[(row - BSZ) * EE + (k - EE)]
                                             : make_float2(0.f, 0.f);
            } else {
                v = *(const float2*)&g_y[row * EE + k];
            }
            arf[i] = v;
        }
    };

    auto loadB = [&](int t) {
        if (MODE == 2) {
            // o-major: lane owns one o, iterates 8 k-words -> warp-coalesced in o
            const int o = bn + oIdx;
            #pragma unroll
            for (int i = 0; i < 8; i++) {
                const int k = koff + t * BK + 2 * (oWh * 8 + i);
                float2 v;
                if (k < EE) {
                    v.x = W0[(k * EE + o) * 2];
                    v.y = W0[((k + 1) * EE + o) * 2];
                } else {
                    v.x = W0[((k - EE) * EE + o) * 2 + 1];
                    v.y = W0[((k + 1 - EE) * EE + o) * 2 + 1];
                }
                brf[i] = v;
            }
        } else {
            const int k = koff + t * BK + 2 * wIdx;
            #pragma unroll
            for (int i = 0; i < 8; i++) {
                const int o = bn + i * 8 + fSub;
                float2 v;
                if (MODE == 0) {
                    // one float4 covers both taps of both k's (k even, aligned)
                    const int kk = (k < EE) ? k : k - EE;
                    const float4 f4 = *(const float4*)&W0[(o * EE + kk) * 2];
                    v = (k < EE) ? make_float2(f4.x, f4.z)
                                 : make_float2(f4.y, f4.w);
                } else if (MODE == 1) {
                    const float* Wp; int oo = o;
                    if (o < EH)          Wp = W0;
                    else if (o < 2 * EH) { Wp = W1; oo = o - EH; }
                    else if (o < 3 * EH) { Wp = W2; oo = o - 2 * EH; }
                    else                 { Wp = W3; oo = o - 3 * EH; }
                    v = *(const float2*)&Wp[oo * EE + k];
                } else {
                    v = *(const float2*)&W0[o * EE + k];
                }
                brf[i] = v;
            }
        }
    };

    auto storeTiles = [&](int nb) {
        #pragma unroll
        for (int i = 0; i < 4; i++) {
            unsigned h, l; bsplit(arf[i], h, l);
            const int off = (i * 8 + fSub) * STR + wIdx;
            AhS[nb][off] = h; AlS[nb][off] = l;
        }
        if (MODE == 2) {
            #pragma unroll
            for (int i = 0; i < 8; i++) {
                unsigned h, l; bsplit(brf[i], h, l);
                const int off = oIdx * STR + oWh * 8 + i;
                BhS[nb][off] = h; BlS[nb][off] = l;
            }
        } else {
            #pragma unroll
            for (int i = 0; i < 8; i++) {
                unsigned h, l; bsplit(brf[i], h, l);
                const int off = (i * 8 + fSub) * STR + wIdx;
                BhS[nb][off] = h; BlS[nb][off] = l;
            }
        }
    };

    float dm[4][4] = {};   // hi*hi accumulators (per n-tile)
    float dc[4][4] = {};   // hi*lo + lo*hi corrections

    loadA(0); loadB(0);
    storeTiles(0);
    __syncthreads();

    int buf = 0;
    for (int t = 0; t < NT; t++) {
        if (t + 1 < NT) { loadA(t + 1); loadB(t + 1); }

        #pragma unroll
        for (int k16 = 0; k16 < 2; k16++) {
            const int wb = k16 * 8 + thr4;
            const int r0i = (rb + grp) * STR + wb;
            const int r1i = (rb + grp + 8) * STR + wb;
            unsigned ah[4], al[4];
            ah[0] = AhS[buf][r0i];     ah[1] = AhS[buf][r1i];
            ah[2] = AhS[buf][r0i + 4]; ah[3] = AhS[buf][r1i + 4];
            al[0] = AlS[buf][r0i];     al[1] = AlS[buf][r1i];
            al[2] = AlS[buf][r0i + 4]; al[3] = AlS[buf][r1i + 4];
            #pragma unroll
            for (int nt = 0; nt < 4; nt++) {
                const int ci = (cbB + nt * 8 + grp) * STR + wb;
                unsigned bh[2] = {BhS[buf][ci], BhS[buf][ci + 4]};
                unsigned bl[2] = {BlS[buf][ci], BlS[buf][ci + 4]};
                mma16(dm[nt], ah, bh);
                mma16(dc[nt], ah, bl);
                mma16(dc[nt], al, bh);
            }
        }

        if (t + 1 < NT) {
            storeTiles(buf ^ 1);
            __syncthreads();
            buf ^= 1;
        }
    }

    // ---- epilogue: atomic accumulate (+bias on z==0) ----------------------------
    float* C = (MODE == 0) ? g_nq : (MODE == 1) ? g_proj
             : (MODE == 2) ? g_y  : Cout;

    #pragma unroll
    for (int nt = 0; nt < 4; nt++) {
        const int col = bn + cbB + nt * 8 + 2 * thr4;
        float bias0, bias1;
        if (MODE == 1) {
            const int seg = col / EH;                  // EH not pow2: no masking
            const float* bp = (seg == 0) ? bb0 : (seg == 1) ? bb1
                            : (seg == 2) ? bb2 : bb3;
            const int ob = col - seg * EH;
            bias0 = bp[ob]; bias1 = bp[ob + 1];
        } else {
            bias0 = bb0[col]; bias1 = bb0[col + 1];
        }
        if (blockIdx.z != 0) { bias0 = 0.f; bias1 = 0.f; }

        const int row = bm + rb + grp;
        atomicAdd(&C[row * N + col],           dm[nt][0] + dc[nt][0] + bias0);
        atomicAdd(&C[row * N + col + 1],       dm[nt][1] + dc[nt][1] + bias1);
        atomicAdd(&C[(row + 8) * N + col],     dm[nt][2] + dc[nt][2] + bias0);
        atomicAdd(&C[(row + 8) * N + col + 1], dm[nt][3] + dc[nt][3] + bias1);
    }
}

// ---------------- dq / dk / de precompute (9216 length-64 dots) -------------
__global__ __launch_bounds__(256)
void dots_kernel(const float* __restrict__ entity,
                 const float* __restrict__ attn_w)
{
    int w    = (blockIdx.x * blockDim.x + threadIdx.x) >> 5;
    int lane = threadIdx.x & 31;
    if (w >= 3 * BHH * LL) return;
    int which = w / (BHH * LL);
    int idx   = w % (BHH * LL);
    float v;
    if (which < 2) {
        int m = idx >> 7, x = idx & 127;
        int b = m / HH, h = m % HH;
        int row = x * BSZ + b;
        int base = (h < 6) ? (row * 1536 + which * EH + h * 64)
                           : (row * 1536 + 3 * EH + (h - 6) * 64);
        const float* wv = attn_w + which * 64;
        v = g_proj[base + lane] * wv[lane] + g_proj[base + lane + 32] * wv[lane + 32];
    } else {
        int i = idx / BHH, s = idx % BHH;
        int b = s / HH, h = s % HH;
        int base = (i * BSZ + b) * EE + h * 64;
        v = entity[base + lane] * attn_w[128 + lane]
          + entity[base + lane + 32] * attn_w[128 + lane + 32];
    }
    #pragma unroll
    for (int off = 16; off; off >>= 1) v += __shfl_down_sync(0xffffffffu, v, off);
    if (lane == 0) {
        if (which == 0)      g_dq[idx] = v;
        else if (which == 1) g_dk[idx] = v;
        else                 g_de[idx] = v;
    }
}

// ---------------- fused attention: 16 rows per block ------------------------
__global__ __launch_bounds__(256)
void attn_kernel(const float* __restrict__ attn_b)
{
    __shared__ float sT[3072];       // dk - de
    __shared__ float sqe[64];        // dq + de for the block's 2 i_src values
    __shared__ __align__(8) float sp[16][128];   // normalized probs

    const int ig  = blockIdx.x;      // 0..7 (16-row group)
    const int bh  = blockIdx.y;      // 0..23
    const int tid = threadIdx.x;
    const int g0  = bh * 16384 + ig * 2048;
    const int i_src0 = g0 / 3072;

    for (int x = tid; x < 3072; x += 256) sT[x] = g_dk[x] - g_de[x];
    if (tid < 48) {
        const int il = tid / 24, s = tid - il * 24;
        const int isrc = min(i_src0 + il, LL - 1);
        sqe[tid] = g_dq[s * 128 + isrc] + g_de[isrc * 24 + s];
    }
    __syncthreads();
    const float bias = attn_b[0];

    const int lane = tid & 31, w = tid >> 5;
    #pragma unroll
    for (int rr = 0; rr < 2; rr++) {
        const int r  = w + rr * 8;
        const int gb = g0 + r * 128;
        float sc[4];
        #pragma unroll
        for (int q = 0; q < 4; q++) {
            const int g    = gb + q * 32 + lane;
            const int isrc = g / 3072;
            const int rem  = g - isrc * 3072;
            const int s    = rem % 24;
            float v = sqe[(isrc - i_src0) * 24 + s] + sT[rem] + bias;
            sc[q] = (v >= 0.f) ? v : 0.01f * v;
        }
        float m = fmaxf(fmaxf(sc[0], sc[1]), fmaxf(sc[2], sc[3]));
        #pragma unroll
        for (int off = 16; off; off >>= 1)
            m = fmaxf(m, __shfl_xor_sync(0xffffffffu, m, off));
        float e[4], sum = 0.f;
        #pragma unroll
        for (int q = 0; q < 4; q++) { e[q] = __expf(sc[q] - m); sum += e[q]; }
        #pragma unroll
        for (int off = 16; off; off >>= 1)
            sum += __shfl_xor_sync(0xffffffffu, sum, off);
        const float inv = 1.f / sum;
        #pragma unroll
        for (int q = 0; q < 4; q++) sp[r][q * 32 + lane] = e[q] * inv;
    }
    __syncthreads();

    const int b = bh / HH, h = bh - (bh / HH) * HH;
    const int off = (h < 6) ? (2 * EH + h * 64) : (3 * EH + (h - 6) * 64);
    const int d  = tid & 63;
    const int r0 = (tid >> 6) * 4;   // 0,4,8,12
    const float* Vp = g_proj + b * 1536 + off + d;

    unsigned long long acc2[4] = {};
    #pragma unroll 4
    for (int jj = 0; jj < 128; jj += 2) {
        const float v0 = Vp[jj * 3072];
        const float v1 = Vp[(jj + 1) * 3072];
        unsigned long long vv;
        PACK2(vv, v0, v1);
        #pragma unroll
        for (int r = 0; r < 4; r++) {
            const unsigned long long pp = *(const unsigned long long*)&sp[r0 + r][jj];
            FMA2(acc2[r], pp, vv);
        }
    }
    #pragma unroll
    for (int r = 0; r < 4; r++) {
        float lo, hi;
        UNPK(lo, hi, acc2[r]);
        const int i2 = ig * 16 + r0 + r;
        g_a[(i2 * BSZ + b) * EE + h * 64 + d] = lo + hi;
    }
}

// ---------------- launcher ---------------------------------------------------
extern "C" void kernel_launch(void* const* d_in, const int* in_sizes, int n_in,
                              void* d_out, int out_size)
{
    const float* query    = (const float*)d_in[0];
    const float* entity   = (const float*)d_in[1];
    const float* conv_w   = (const float*)d_in[2];
    const float* conv_b   = (const float*)d_in[3];
    const float* q_w      = (const float*)d_in[4];
    const float* q_b      = (const float*)d_in[5];
    const float* k_w      = (const float*)d_in[6];
    const float* k_b      = (const float*)d_in[7];
    const float* v_w      = (const float*)d_in[8];
    const float* v_b      = (const float*)d_in[9];
    const float* e_w      = (const float*)d_in[10];
    const float* e_b      = (const float*)d_in[11];
    const float* attn_w   = (const float*)d_in[12];
    const float* attn_b   = (const float*)d_in[13];
    const float* deconv_w = (const float*)d_in[14];
    const float* deconv_b = (const float*)d_in[15];
    const float* out_w    = (const float*)d_in[16];
    const float* out_b    = (const float*)d_in[17];
    float* out = (float*)d_out;

    init_a_kernel<<<384, 256>>>();                 // slot 0
    init_b_kernel<<<576, 256>>>(out);              // slot 1
    gemm_kernel<0, 8><<<dim3(12, 8, 8), 128>>>(query, conv_w, nullptr, nullptr, nullptr,
                                               conv_b, nullptr, nullptr, nullptr, nullptr);  // slot 2 (profiled next)
    gemm_kernel<1, 4><<<dim3(24, 8, 4), 128>>>(entity, q_w, k_w, v_w, e_w,
                                               q_b, k_b, v_b, e_b, nullptr);                 // slot 3 (profiled)
    dots_kernel<<<1152, 256>>>(entity, attn_w);
    attn_kernel<<<dim3(8, BHH), 256>>>(attn_b);
    gemm_kernel<2, 8><<<dim3(12, 8, 8), 128>>>(nullptr, deconv_w, nullptr, nullptr, nullptr,
                                               deconv_b, nullptr, nullptr, nullptr, nullptr);
    gemm_kernel<3, 4><<<dim3(12, 8, 4), 128>>>(nullptr, out_w, nullptr, nullptr, nullptr,
                                               out_b, nullptr, nullptr, nullptr, out);
}